// round 1
// baseline (speedup 1.0000x reference)
#include <cuda_runtime.h>

#define BATCH 8
#define HH 384
#define WW 384
#define PHI 32
#define RHO 64
#define NSEG 8
#define RPS (HH / NSEG)   /* 48 rows per segment, divisible by 3 */
#define GCH 16            /* channels per thread */
#define NGRP (RHO / GCH)  /* 4 channel groups */

// out[p,c] = relu( (1/9) * sum_{n in 3x3} U[q_n][c] + b3[c] )
// with U[v] = (relu(v*w1+b1) @ w2 + b2) @ w3 and q in {0..7}.
__global__ void __launch_bounds__(128)
lpmp_deepset_kernel(const float* __restrict__ x,  const float* __restrict__ w1,
                    const float* __restrict__ b1, const float* __restrict__ w2,
                    const float* __restrict__ b2, const float* __restrict__ w3,
                    const float* __restrict__ b3, float* __restrict__ out)
{
    __shared__ __align__(16) float Tsh[8][33];  // T[q][k] = b2[k] + sum_j relu(q*w1[j]+b1[j])*w2[j][k]
    __shared__ __align__(16) float U1[8][20];   // U'[q][c] for this block's 16 channels, scaled 1/9
                                                // row stride 20 floats -> 8 rows hit 8 disjoint bank windows

    const int tid   = threadIdx.x;
    const int xtile = blockIdx.x;
    const int b     = blockIdx.y / NSEG;
    const int seg   = blockIdx.y % NSEG;
    const int g     = blockIdx.z;

    // ---- build the 8-entry table (tiny) ----
    #pragma unroll
    for (int e = tid; e < 8 * PHI; e += 128) {
        const int q = e >> 5, k = e & 31;
        const float fq = (float)q;
        float acc = b2[k];
        #pragma unroll
        for (int j = 0; j < PHI; j++) {
            float hv = fmaxf(fmaf(fq, w1[j], b1[j]), 0.0f);
            acc = fmaf(hv, w2[j * PHI + k], acc);
        }
        Tsh[q][k] = acc;
    }
    __syncthreads();
    {
        const int q = tid >> 4, c = tid & 15;   // 128 threads == 8*16 entries
        float acc = 0.0f;
        #pragma unroll
        for (int k = 0; k < PHI; k++)
            acc = fmaf(Tsh[q][k], w3[k * RHO + g * GCH + c], acc);
        U1[q][c] = acc * (1.0f / 9.0f);
    }
    __syncthreads();

    float b3r[GCH];
    #pragma unroll
    for (int c = 0; c < GCH; c++) b3r[c] = b3[g * GCH + c];

    const int x0 = xtile * 128 + tid;                  // this thread's column
    const float* __restrict__ xin = x + b * (HH * WW);
    float* __restrict__ ob = out + ((size_t)(b * RHO + g * GCH)) * (HH * WW) + x0;

    const float QS = 255.0f / 32.0f;
    const int y0 = seg * RPS;

    float R[3][GCH];

    // Row sum of table entries for columns x0-1, x0, x0+1 at row yy.
    auto rowsum = [&](int yy, float* __restrict__ N) {
        int c0 = 0, c1 = 0, c2 = 0;
        if (yy >= 0 && yy < HH) {
            const float* row = xin + yy * WW;
            float v1 = __ldg(row + x0);
            float v0 = (x0 > 0)      ? __ldg(row + x0 - 1) : 0.0f;
            float v2 = (x0 < WW - 1) ? __ldg(row + x0 + 1) : 0.0f;
            // values are >= 0 so int-cast == floor; clamp guards shared OOB
            c0 = min((int)(v0 * QS), 7);
            c1 = min((int)(v1 * QS), 7);
            c2 = min((int)(v2 * QS), 7);
        }
        const float4* p0 = (const float4*)(&U1[c0][0]);
        const float4* p1 = (const float4*)(&U1[c1][0]);
        const float4* p2 = (const float4*)(&U1[c2][0]);
        #pragma unroll
        for (int v = 0; v < 4; v++) {
            float4 a = p0[v], bb = p1[v], cc = p2[v];
            N[4 * v + 0] = a.x + bb.x + cc.x;
            N[4 * v + 1] = a.y + bb.y + cc.y;
            N[4 * v + 2] = a.z + bb.z + cc.z;
            N[4 * v + 3] = a.w + bb.w + cc.w;
        }
    };

    rowsum(y0 - 1, R[0]);
    rowsum(y0,     R[1]);

    for (int y = y0; y < y0 + RPS; y += 3) {
        #pragma unroll
        for (int k = 0; k < 3; k++) {
            const int yy = y + k;
            float* P = R[k];
            float* C = R[(k + 1) % 3];
            float* N = R[(k + 2) % 3];
            rowsum(yy + 1, N);
            float* orow = ob + yy * WW;
            #pragma unroll
            for (int c = 0; c < GCH; c++) {
                float s = fmaxf(P[c] + C[c] + N[c] + b3r[c], 0.0f);
                orow[c * (HH * WW)] = s;
            }
        }
    }
}

extern "C" void kernel_launch(void* const* d_in, const int* in_sizes, int n_in,
                              void* d_out, int out_size) {
    const float* x  = (const float*)d_in[0];
    const float* w1 = (const float*)d_in[1];
    const float* b1 = (const float*)d_in[2];
    const float* w2 = (const float*)d_in[3];
    const float* b2 = (const float*)d_in[4];
    const float* w3 = (const float*)d_in[5];
    const float* b3 = (const float*)d_in[6];
    float* out = (float*)d_out;

    dim3 grid(WW / 128, BATCH * NSEG, NGRP);
    lpmp_deepset_kernel<<<grid, 128>>>(x, w1, b1, w2, b2, w3, b3, out);
}